// round 12
// baseline (speedup 1.0000x reference)
#include <cuda_runtime.h>
#include <cuda_fp16.h>
#include <cstdint>
#include <math.h>

#define BATCH 8
#define NSEQ  1024
#define CDIM  768
#define NHEAD 12
#define DHEAD 64
#define MROWS 8192
#define KDIM  768
// Q pre-scale: 1/sqrt(64) * log2(e)  (attention exp done as exp2)
#define QK_SCALE_LOG2E 0.18033688011112042f

typedef unsigned long long u64;
typedef unsigned int u32;

// ---------------------------------------------------------------------------
// scratch globals (allocation-free) — all single fp16
// ---------------------------------------------------------------------------
__device__ __half g_x[MROWS * CDIM];
__device__ __half g_qw[3 * CDIM * CDIM];
__device__ __half g_pw[CDIM * CDIM];
__device__ __half g_Qh[BATCH * NHEAD * NSEQ * DHEAD];  // pre-scaled by SCALE*log2e
__device__ __half g_Kh[BATCH * NHEAD * NSEQ * DHEAD];
__device__ __half g_Vt[BATCH * NHEAD * DHEAD * NSEQ];  // [B,H,D,N]
__device__ __half g_O[MROWS * CDIM];                   // attn out [B,N,C]

// ---------------------------------------------------------------------------
// PTX helpers — sm_80-era instruction set (valid under compute_103)
// ---------------------------------------------------------------------------
__device__ __forceinline__ u32 smem_u32(const void* p) {
    u32 a;
    asm("{ .reg .u64 t; cvta.to.shared.u64 t, %1; cvt.u32.u64 %0, t; }"
        : "=r"(a) : "l"(p));
    return a;
}

#define CP_ASYNC16(dst, src) \
    asm volatile("cp.async.cg.shared.global [%0], [%1], 16;" \
        :: "r"(dst), "l"(src) : "memory")
#define CP_COMMIT() asm volatile("cp.async.commit_group;" ::: "memory")
#define CP_WAIT1()  asm volatile("cp.async.wait_group 1;" ::: "memory")

__device__ __forceinline__ void ldmx4(u32& r0, u32& r1, u32& r2, u32& r3, u32 addr) {
    asm volatile("ldmatrix.sync.aligned.m8n8.x4.shared.b16 {%0,%1,%2,%3}, [%4];"
        : "=r"(r0), "=r"(r1), "=r"(r2), "=r"(r3) : "r"(addr));
}

__device__ __forceinline__ void mma16816(float* c, const u32* a, const u32* b) {
    asm volatile(
        "mma.sync.aligned.m16n8k16.row.col.f32.f16.f16.f32 "
        "{%0,%1,%2,%3}, {%4,%5,%6,%7}, {%8,%9}, {%0,%1,%2,%3};"
        : "+f"(c[0]), "+f"(c[1]), "+f"(c[2]), "+f"(c[3])
        : "r"(a[0]), "r"(a[1]), "r"(a[2]), "r"(a[3]), "r"(b[0]), "r"(b[1]));
}

// exp2 of a float pair via fp16x2; returns packed half2 bits
__device__ __forceinline__ u32 exp2_h2(float a, float b) {
    __half2 h = __floats2half2_rn(a, b);
    __half2 e = h2exp2(h);
    return *(u32*)&e;
}

// ---------------------------------------------------------------------------
// Kernel 0: fused fp32 -> fp16 round for x and qkv_w (pw handled in attn)
// ---------------------------------------------------------------------------
#define N_X  (MROWS * CDIM)
#define N_QW (3 * CDIM * CDIM)
#define N_PW (CDIM * CDIM)

__global__ __launch_bounds__(256) void cvt_all_kernel(
    const float* __restrict__ x, const float* __restrict__ qw)
{
    int i = (blockIdx.x * 256 + threadIdx.x) * 4;
    const float* src;
    __half* dst;
    if (i < N_X)             { src = x + i;          dst = g_x + i; }
    else if (i < N_X + N_QW) { src = qw + (i - N_X); dst = g_qw + (i - N_X); }
    else return;
    float4 v = *(const float4*)src;
    union { __half h[4]; uint2 u; } uh;
    uh.h[0] = __float2half(v.x); uh.h[1] = __float2half(v.y);
    uh.h[2] = __float2half(v.z); uh.h[3] = __float2half(v.w);
    *(uint2*)dst = uh.u;
}

// ---------------------------------------------------------------------------
// Kernel 1: QKV GEMM (mma.sync fp16, fp32 accum).
// Block 128x128, 8 warps of 64x32, K-slab 64, single-barrier 3-stage pipeline.
// Epilogue: Q(*scale*log2e)/K -> [B,H,N,D] u32 stores; V -> smem transpose,
// then coalesced 16B rows into g_Vt [B,H,D,N].
// ---------------------------------------------------------------------------
#define ARR_BYTES   18432           // 128 * 144
#define STAGE_BYTES 36864           // 2 arrays
#define SMEM_DYN    110592          // 3 stages
#define NSLAB       12              // 768 / 64
#define VT_STRIDE   136             // halves per smem row (128 + 8 pad)

__global__ __launch_bounds__(256, 2) void qkv_tc_kernel()
{
    extern __shared__ char smem_raw[];
    const u32 smem_base = smem_u32(smem_raw);

    const int tid = threadIdx.x;
    const int wid = tid >> 5;
    const int lane = tid & 31;
    const int warp_m = wid >> 2;
    const int warp_n = wid & 3;
    const int m0 = blockIdx.y * 128;
    const int n0 = blockIdx.x * 128;

    auto load_slab = [&](int st, int kele) {
        const u32 stb = smem_base + st * STAGE_BYTES;
#pragma unroll
        for (int e = tid; e < 2048; e += 256) {
            const int arr = e >> 10;         // 0:A(x) 1:B(qw)
            const int i = e & 1023;
            const int row = i >> 3, ch = i & 7;
            const __half* base = arr ? g_qw : g_x;
            const int grow = (arr ? n0 : m0) + row;
            const __half* src = base + (size_t)grow * KDIM + kele + ch * 8;
            const u32 dst = stb + arr * ARR_BYTES + row * 144 + ch * 16;
            CP_ASYNC16(dst, src);
        }
    };

    float C[4][4][4];
#pragma unroll
    for (int i = 0; i < 4; i++)
#pragma unroll
        for (int j = 0; j < 4; j++)
#pragma unroll
            for (int r = 0; r < 4; r++) C[i][j][r] = 0.0f;

    load_slab(0, 0);  CP_COMMIT();
    load_slab(1, 64); CP_COMMIT();

    const u32 a_row = warp_m * 64 + (lane & 15);
    const u32 a_colh = ((lane >> 4) & 1) * 16;
    const u32 b_row = warp_n * 32 + (lane & 7) + ((lane & 16) >> 1);
    const u32 b_colh = ((lane >> 3) & 1) * 16;

    int stage = 0, lstage = 2;
    for (int s = 0; s < NSLAB; s++) {
        CP_WAIT1();
        __syncthreads();
        if (s + 2 < NSLAB) load_slab(lstage, (s + 2) * 64);
        CP_COMMIT();

        const u32 stb = smem_base + stage * STAGE_BYTES;
#pragma unroll
        for (int kk = 0; kk < 4; kk++) {
            const u32 k0b = kk * 32;
            u32 Bv[4][2];
#pragma unroll
            for (int np = 0; np < 2; np++) {
                const u32 badr = stb + ARR_BYTES +
                                 (b_row + np * 16) * 144 + k0b + b_colh;
                u32 r0, r1, r2, r3;
                ldmx4(r0, r1, r2, r3, badr);
                Bv[np * 2][0] = r0; Bv[np * 2][1] = r1;
                Bv[np * 2 + 1][0] = r2; Bv[np * 2 + 1][1] = r3;
            }
            u32 A[4][4];
#pragma unroll
            for (int ms = 0; ms < 4; ms++) {
                const u32 aoff = (a_row + ms * 16) * 144 + k0b + a_colh;
                ldmx4(A[ms][0], A[ms][1], A[ms][2], A[ms][3], stb + aoff);
            }
#pragma unroll
            for (int ms = 0; ms < 4; ms++)
#pragma unroll
                for (int ns = 0; ns < 4; ns++)
                    mma16816(C[ms][ns], A[ms], Bv[ns]);
        }
        stage = (stage == 2) ? 0 : stage + 1;
        lstage = (lstage == 2) ? 0 : lstage + 1;
    }

    const int which = n0 / 768;         // constant per CTA (n0 multiple of 128)
    const int r_in = lane >> 2;
    const int c_in = (lane & 3) * 2;
    const int b = m0 >> 10;
    const int nloc0 = m0 & 1023;

    if (which < 2) {
        // Q or K: direct u32 stores, [B,H,N,D]
        __half* dstbase = (which == 0) ? g_Qh : g_Kh;
        const float sc = (which == 0) ? QK_SCALE_LOG2E : 1.0f;
#pragma unroll
        for (int ms = 0; ms < 4; ms++) {
#pragma unroll
            for (int ns = 0; ns < 4; ns++) {
                const int col = n0 - which * 768 + warp_n * 32 + ns * 8 + c_in;
                const int h = col >> 6, d = col & 63;
#pragma unroll
                for (int half_ = 0; half_ < 2; half_++) {
                    const int row = m0 + warp_m * 64 + ms * 16 + r_in + half_ * 8;
                    const int n = row & 1023;
                    union { __half h[2]; u32 u; } hh;
                    hh.h[0] = __float2half(C[ms][ns][half_ * 2 + 0] * sc);
                    hh.h[1] = __float2half(C[ms][ns][half_ * 2 + 1] * sc);
                    const size_t idx = ((size_t)(b * NHEAD + h) * NSEQ + n) * DHEAD + d;
                    *(u32*)(dstbase + idx) = hh.u;
                }
            }
        }
    } else {
        // V: transpose through smem, then coalesced 16B rows to g_Vt [B,H,D,N]
        __syncthreads();   // all warps past their last smem reads
        __half* Vs = (__half*)smem_raw;   // [128 clocal][VT_STRIDE]
#pragma unroll
        for (int ms = 0; ms < 4; ms++) {
#pragma unroll
            for (int ns = 0; ns < 4; ns++) {
                const int cl = warp_n * 32 + ns * 8 + c_in;
#pragma unroll
                for (int half_ = 0; half_ < 2; half_++) {
                    const int rl = warp_m * 64 + ms * 16 + r_in + half_ * 8;
                    Vs[cl * VT_STRIDE + rl]       = __float2half(C[ms][ns][half_ * 2 + 0]);
                    Vs[(cl + 1) * VT_STRIDE + rl] = __float2half(C[ms][ns][half_ * 2 + 1]);
                }
            }
        }
        __syncthreads();
        // copy out: 128 rows (clocal) x 16 chunks of 16B
        const int hbase = (n0 - 1536) >> 6;
#pragma unroll
        for (int j = tid; j < 2048; j += 256) {
            const int cl = j >> 4, c16 = j & 15;
            const int h = hbase + (cl >> 6), d = cl & 63;
            uint4 v = *(uint4*)(Vs + cl * VT_STRIDE + c16 * 8);
            __half* dst = g_Vt + ((size_t)(b * NHEAD + h) * DHEAD + d) * NSEQ
                          + nloc0 + c16 * 8;
            *(uint4*)dst = v;
        }
    }
}

// ---------------------------------------------------------------------------
// Kernel 1b: proj GEMM, tile 128(M) x 64(N) to soften wave quantization.
// 8 warps as 2m x 4n, warp tile 64x16.  Single-barrier 3-stage pipeline.
// ---------------------------------------------------------------------------
#define PJ_A_BYTES   18432          // 128 * 144
#define PJ_B_BYTES   9216           // 64 * 144
#define PJ_STAGE     27648
#define PJ_SMEM      82944          // 3 stages

__global__ __launch_bounds__(256, 2) void proj_tc_kernel(
    const float* __restrict__ bias, float* __restrict__ out)
{
    extern __shared__ char smem_raw[];
    const u32 smem_base = smem_u32(smem_raw);

    const int tid = threadIdx.x;
    const int wid = tid >> 5;
    const int lane = tid & 31;
    const int warp_m = wid >> 2;      // 0..1
    const int warp_n = wid & 3;       // 0..3
    const int m0 = blockIdx.y * 128;
    const int n0 = blockIdx.x * 64;

    auto load_slab = [&](int st, int kele) {
        const u32 stb = smem_base + st * PJ_STAGE;
#pragma unroll
        for (int e = tid; e < 1536; e += 256) {
            const bool isB = (e >= 1024);
            const int i = isB ? (e - 1024) : e;
            const int row = i >> 3, ch = i & 7;
            const __half* base = isB ? g_pw : g_O;
            const int grow = (isB ? n0 : m0) + row;
            const __half* src = base + (size_t)grow * KDIM + kele + ch * 8;
            const u32 dst = stb + (isB ? PJ_A_BYTES : 0) + row * 144 + ch * 16;
            CP_ASYNC16(dst, src);
        }
    };

    float C[4][2][4];
#pragma unroll
    for (int i = 0; i < 4; i++)
#pragma unroll
        for (int j = 0; j < 2; j++)
#pragma unroll
            for (int r = 0; r < 4; r++) C[i][j][r] = 0.0f;

    load_slab(0, 0);  CP_COMMIT();
    load_slab(1, 64); CP_COMMIT();

    const u32 a_row = warp_m * 64 + (lane & 15);
    const u32 a_colh = ((lane >> 4) & 1) * 16;
    const u32 b_row = warp_n * 16 + (lane & 7) + ((lane & 16) >> 1);
    const u32 b_colh = ((lane >> 3) & 1) * 16;

    int stage = 0, lstage = 2;
    for (int s = 0; s < NSLAB; s++) {
        CP_WAIT1();
        __syncthreads();
        if (s + 2 < NSLAB) load_slab(lstage, (s + 2) * 64);
        CP_COMMIT();

        const u32 stb = smem_base + stage * PJ_STAGE;
#pragma unroll
        for (int kk = 0; kk < 4; kk++) {
            const u32 k0b = kk * 32;
            u32 Bv[2][2];
            {
                const u32 badr = stb + PJ_A_BYTES + b_row * 144 + k0b + b_colh;
                u32 r0, r1, r2, r3;
                ldmx4(r0, r1, r2, r3, badr);
                Bv[0][0] = r0; Bv[0][1] = r1;
                Bv[1][0] = r2; Bv[1][1] = r3;
            }
            u32 A[4][4];
#pragma unroll
            for (int ms = 0; ms < 4; ms++) {
                const u32 aoff = (a_row + ms * 16) * 144 + k0b + a_colh;
                ldmx4(A[ms][0], A[ms][1], A[ms][2], A[ms][3], stb + aoff);
            }
#pragma unroll
            for (int ms = 0; ms < 4; ms++)
#pragma unroll
                for (int ns = 0; ns < 2; ns++)
                    mma16816(C[ms][ns], A[ms], Bv[ns]);
        }
        stage = (stage == 2) ? 0 : stage + 1;
        lstage = (lstage == 2) ? 0 : lstage + 1;
    }

    const int r_in = lane >> 2;
    const int c_in = (lane & 3) * 2;
#pragma unroll
    for (int ms = 0; ms < 4; ms++) {
#pragma unroll
        for (int ns = 0; ns < 2; ns++) {
            const int col = n0 + warp_n * 16 + ns * 8 + c_in;
            const float2 bb = *(const float2*)(bias + col);
#pragma unroll
            for (int half_ = 0; half_ < 2; half_++) {
                const int row = m0 + warp_m * 64 + ms * 16 + r_in + half_ * 8;
                float2 w = make_float2(C[ms][ns][half_ * 2 + 0] + bb.x,
                                       C[ms][ns][half_ * 2 + 1] + bb.y);
                *(float2*)(out + (size_t)row * 768 + col) = w;
            }
        }
    }
}

// ---------------------------------------------------------------------------
// Kernel 2: flash attention (max-free exp2 softmax, fp32 accum).
// 8 warps/CTA, Q-tile 128, K-tile 64, single-barrier 3-stage pipeline.
// Side job: converts proj_w fp32->fp16 (one 16B chunk per thread), overlapped.
// ---------------------------------------------------------------------------
#define FA_Q      18432              // 128 rows * 144B
#define FA_ARR    9216               // 64 rows * 144B
#define FA_STAGE  18432              // 2 arrays (K, Vt)
#define FA_SMEM   (FA_Q + 3 * FA_STAGE)   // 73728
#define NT        (NSEQ / 64)        // 16

__global__ __launch_bounds__(256) void flash_attn_tc_kernel(
    const float* __restrict__ pw_f32)
{
    extern __shared__ char smem_raw[];
    const u32 S0 = smem_u32(smem_raw);

    const int tid = threadIdx.x;
    const int w = tid >> 5;
    const int lane = tid & 31;
    const int qt = blockIdx.x;        // 0..7
    const int h  = blockIdx.y;
    const int b  = blockIdx.z;
    const size_t bh = (size_t)(b * NHEAD + h);

    const __half* Qg = g_Qh + (bh * NSEQ + qt * 128) * DHEAD;
    const __half* Kg = g_Kh + bh * NSEQ * DHEAD;
    const __half* Vg = g_Vt + bh * DHEAD * NSEQ;

#pragma unroll
    for (int e = tid; e < 1024; e += 256) {
        const int r = e >> 3, ch = e & 7;
        CP_ASYNC16(S0 + r * 144 + ch * 16, Qg + r * DHEAD + ch * 8);
    }

    auto load_kv = [&](int st, int t) {
        const u32 stb = S0 + FA_Q + st * FA_STAGE;
#pragma unroll
        for (int e = tid; e < 1024; e += 256) {
            const int arr = e >> 9;          // 0:K 1:Vt
            const int i = e & 511;
            const int r = i >> 3, ch = i & 7;
            const __half* src;
            if (arr == 0) src = Kg + (size_t)(t * 64 + r) * DHEAD + ch * 8;
            else          src = Vg + (size_t)r * NSEQ + t * 64 + ch * 8;
            CP_ASYNC16(stb + arr * FA_ARR + r * 144 + ch * 16, src);
        }
    };

    load_kv(0, 0); CP_COMMIT();
    load_kv(1, 1); CP_COMMIT();

    // side job: convert proj_w (overlaps with cp.async arrivals)
    {
        const int flat = (blockIdx.z * 12 + blockIdx.y) * 8 + blockIdx.x;
        const int tg = flat * 256 + tid;
        if (tg < N_PW / 4) {
            const int i = tg * 4;
            float4 v = *(const float4*)(pw_f32 + i);
            union { __half h[4]; uint2 u; } uh;
            uh.h[0] = __float2half(v.x); uh.h[1] = __float2half(v.y);
            uh.h[2] = __float2half(v.z); uh.h[3] = __float2half(v.w);
            *(uint2*)(g_pw + i) = uh.u;
        }
    }

    float O[8][4];
#pragma unroll
    for (int i = 0; i < 8; i++)
#pragma unroll
        for (int j = 0; j < 4; j++) O[i][j] = 0.0f;
    float l0 = 0.0f, l1 = 0.0f;

    const u32 qbase = S0 + w * 16 * 144;
    const u32 a_rowoff = (lane & 15) * 144 + ((lane >> 4) & 1) * 16;
    const u32 b_rowsel = (lane & 7) + ((lane & 16) >> 1);
    const u32 b_colh = ((lane >> 3) & 1) * 16;

    int stage = 0, lstage = 2;
    for (int t = 0; t < NT; t++) {
        CP_WAIT1();
        __syncthreads();
        if (t + 2 < NT) load_kv(lstage, t + 2);
        CP_COMMIT();

        const u32 stb = S0 + FA_Q + stage * FA_STAGE;
        const u32 K_s = stb, V_s = stb + FA_ARR;

        float Sc[8][4];
#pragma unroll
        for (int j = 0; j < 8; j++)
#pragma unroll
            for (int r = 0; r < 4; r++) Sc[j][r] = 0.0f;

#pragma unroll
        for (int kk = 0; kk < 4; kk++) {
            const u32 k0b = kk * 32;
            u32 Aq[4];
            ldmx4(Aq[0], Aq[1], Aq[2], Aq[3], qbase + a_rowoff + k0b);
#pragma unroll
            for (int kb = 0; kb < 4; kb++) {
                const u32 roff = (kb * 16 + b_rowsel) * 144 + k0b + b_colh;
                u32 r0, r1, r2, r3;
                ldmx4(r0, r1, r2, r3, K_s + roff);
                u32 b0[2] = {r0, r1}, b1[2] = {r2, r3};
                mma16816(Sc[kb * 2],     Aq, b0);
                mma16816(Sc[kb * 2 + 1], Aq, b1);
            }
        }

        u32 Pp01[8], Pp23[8];
#pragma unroll
        for (int j = 0; j < 8; j++) {
            Pp01[j] = exp2_h2(Sc[j][0], Sc[j][1]);
            Pp23[j] = exp2_h2(Sc[j][2], Sc[j][3]);
            float2 f0 = __half22float2(*(__half2*)&Pp01[j]);
            float2 f1 = __half22float2(*(__half2*)&Pp23[j]);
            l0 += f0.x + f0.y;
            l1 += f1.x + f1.y;
        }

#pragma unroll
        for (int kk2 = 0; kk2 < 4; kk2++) {
            u32 PA[4] = {Pp01[2 * kk2], Pp23[2 * kk2],
                         Pp01[2 * kk2 + 1], Pp23[2 * kk2 + 1]};
            const u32 k0b = kk2 * 32;
#pragma unroll
            for (int ds = 0; ds < 4; ds++) {
                const u32 roff = (ds * 16 + b_rowsel) * 144 + k0b + b_colh;
                u32 r0, r1, r2, r3;
                ldmx4(r0, r1, r2, r3, V_s + roff);
                u32 v0[2] = {r0, r1}, v1[2] = {r2, r3};
                mma16816(O[ds * 2],     PA, v0);
                mma16816(O[ds * 2 + 1], PA, v1);
            }
        }

        stage = (stage == 2) ? 0 : stage + 1;
        lstage = (lstage == 2) ? 0 : lstage + 1;
    }

    l0 += __shfl_xor_sync(0xffffffffu, l0, 1);
    l0 += __shfl_xor_sync(0xffffffffu, l0, 2);
    l1 += __shfl_xor_sync(0xffffffffu, l1, 1);
    l1 += __shfl_xor_sync(0xffffffffu, l1, 2);
    const float inv0 = 1.0f / l0, inv1 = 1.0f / l1;

    const int r0 = lane >> 2;
    const int nrow0 = qt * 128 + w * 16 + r0;
    const int colb = h * 64 + (lane & 3) * 2;
#pragma unroll
    for (int ds = 0; ds < 8; ds++) {
        const int col = colb + ds * 8;
        __half2 h0 = __floats2half2_rn(O[ds][0] * inv0, O[ds][1] * inv0);
        __half2 h1 = __floats2half2_rn(O[ds][2] * inv1, O[ds][3] * inv1);
        const size_t i0 = (size_t)(b * NSEQ + nrow0) * CDIM + col;
        const size_t i1 = (size_t)(b * NSEQ + nrow0 + 8) * CDIM + col;
        *(__half2*)(g_O + i0) = h0;
        *(__half2*)(g_O + i1) = h1;
    }
}

// ---------------------------------------------------------------------------
extern "C" void kernel_launch(void* const* d_in, const int* in_sizes, int n_in,
                              void* d_out, int out_size)
{
    const float* x      = (const float*)d_in[0];
    const float* qkv_w  = (const float*)d_in[1];
    const float* proj_w = (const float*)d_in[2];
    const float* proj_b = (const float*)d_in[3];
    float* out = (float*)d_out;

    cudaFuncSetAttribute(qkv_tc_kernel,
                         cudaFuncAttributeMaxDynamicSharedMemorySize, SMEM_DYN);
    cudaFuncSetAttribute(proj_tc_kernel,
                         cudaFuncAttributeMaxDynamicSharedMemorySize, PJ_SMEM);
    cudaFuncSetAttribute(flash_attn_tc_kernel,
                         cudaFuncAttributeMaxDynamicSharedMemorySize, FA_SMEM);

    const int ncvt = (N_X + N_QW) / 4;
    cvt_all_kernel<<<(ncvt + 255) / 256, 256>>>(x, qkv_w);

    // QKV projection -> Q(*scale*log2e)/K [B,H,N,D], Vt [B,H,D,N]
    qkv_tc_kernel<<<dim3(2304 / 128, MROWS / 128), 256, SMEM_DYN>>>();

    // Flash attention (+ pw conversion side job)
    flash_attn_tc_kernel<<<dim3(NSEQ / 128, NHEAD, BATCH), 256, FA_SMEM>>>(proj_w);

    // Output projection (+bias) -> d_out, 128x64 tiles
    proj_tc_kernel<<<dim3(768 / 64, MROWS / 128), 256, PJ_SMEM>>>(proj_b, out);
}

// round 13
// speedup vs baseline: 1.0463x; 1.0463x over previous
#include <cuda_runtime.h>
#include <cuda_fp16.h>
#include <cstdint>
#include <math.h>

#define BATCH 8
#define NSEQ  1024
#define CDIM  768
#define NHEAD 12
#define DHEAD 64
#define MROWS 8192
#define KDIM  768
// Q pre-scale: 1/sqrt(64) * log2(e)  (attention exp done as exp2)
#define QK_SCALE_LOG2E 0.18033688011112042f

typedef unsigned long long u64;
typedef unsigned int u32;

// ---------------------------------------------------------------------------
// scratch globals (allocation-free) — all single fp16
// ---------------------------------------------------------------------------
__device__ __half g_x[MROWS * CDIM];
__device__ __half g_qw[3 * CDIM * CDIM];
__device__ __half g_pw[CDIM * CDIM];
__device__ __half g_Qh[BATCH * NHEAD * NSEQ * DHEAD];  // pre-scaled by SCALE*log2e
__device__ __half g_Kh[BATCH * NHEAD * NSEQ * DHEAD];
__device__ __half g_Vt[BATCH * NHEAD * DHEAD * NSEQ];  // [B,H,D,N]
__device__ __half g_O[MROWS * CDIM];                   // attn out [B,N,C]

// ---------------------------------------------------------------------------
// PTX helpers — sm_80-era instruction set (valid under compute_103)
// ---------------------------------------------------------------------------
__device__ __forceinline__ u32 smem_u32(const void* p) {
    u32 a;
    asm("{ .reg .u64 t; cvta.to.shared.u64 t, %1; cvt.u32.u64 %0, t; }"
        : "=r"(a) : "l"(p));
    return a;
}

#define CP_ASYNC16(dst, src) \
    asm volatile("cp.async.cg.shared.global [%0], [%1], 16;" \
        :: "r"(dst), "l"(src) : "memory")
#define CP_COMMIT() asm volatile("cp.async.commit_group;" ::: "memory")
#define CP_WAIT1()  asm volatile("cp.async.wait_group 1;" ::: "memory")

__device__ __forceinline__ void ldmx4(u32& r0, u32& r1, u32& r2, u32& r3, u32 addr) {
    asm volatile("ldmatrix.sync.aligned.m8n8.x4.shared.b16 {%0,%1,%2,%3}, [%4];"
        : "=r"(r0), "=r"(r1), "=r"(r2), "=r"(r3) : "r"(addr));
}

__device__ __forceinline__ void mma16816(float* c, const u32* a, const u32* b) {
    asm volatile(
        "mma.sync.aligned.m16n8k16.row.col.f32.f16.f16.f32 "
        "{%0,%1,%2,%3}, {%4,%5,%6,%7}, {%8,%9}, {%0,%1,%2,%3};"
        : "+f"(c[0]), "+f"(c[1]), "+f"(c[2]), "+f"(c[3])
        : "r"(a[0]), "r"(a[1]), "r"(a[2]), "r"(a[3]), "r"(b[0]), "r"(b[1]));
}

// exp2 of a float pair via fp16x2; returns packed half2 bits
__device__ __forceinline__ u32 exp2_h2(float a, float b) {
    __half2 h = __floats2half2_rn(a, b);
    __half2 e = h2exp2(h);
    return *(u32*)&e;
}

// ---------------------------------------------------------------------------
// Kernel 0: fused fp32 -> fp16 round for x and qkv_w (pw handled in attn)
// ---------------------------------------------------------------------------
#define N_X  (MROWS * CDIM)
#define N_QW (3 * CDIM * CDIM)
#define N_PW (CDIM * CDIM)

__global__ __launch_bounds__(256) void cvt_all_kernel(
    const float* __restrict__ x, const float* __restrict__ qw)
{
    int i = (blockIdx.x * 256 + threadIdx.x) * 4;
    const float* src;
    __half* dst;
    if (i < N_X)             { src = x + i;          dst = g_x + i; }
    else if (i < N_X + N_QW) { src = qw + (i - N_X); dst = g_qw + (i - N_X); }
    else return;
    float4 v = *(const float4*)src;
    union { __half h[4]; uint2 u; } uh;
    uh.h[0] = __float2half(v.x); uh.h[1] = __float2half(v.y);
    uh.h[2] = __float2half(v.z); uh.h[3] = __float2half(v.w);
    *(uint2*)dst = uh.u;
}

// ---------------------------------------------------------------------------
// Kernel 1: QKV GEMM (mma.sync fp16, fp32 accum).
// Block 128x128, 8 warps of 64x32, K-slab 64, single-barrier 3-stage pipeline.
// Epilogue: Q(*scale*log2e)/K -> [B,H,N,D] u32 stores; V -> smem transpose,
// then coalesced 16B rows into g_Vt [B,H,D,N].
// ---------------------------------------------------------------------------
#define ARR_BYTES   18432           // 128 * 144
#define STAGE_BYTES 36864           // 2 arrays
#define SMEM_DYN    110592          // 3 stages
#define NSLAB       12              // 768 / 64
#define VT_STRIDE   136             // halves per smem row (128 + 8 pad)

__global__ __launch_bounds__(256, 2) void qkv_tc_kernel()
{
    extern __shared__ char smem_raw[];
    const u32 smem_base = smem_u32(smem_raw);

    const int tid = threadIdx.x;
    const int wid = tid >> 5;
    const int lane = tid & 31;
    const int warp_m = wid >> 2;
    const int warp_n = wid & 3;
    const int m0 = blockIdx.y * 128;
    const int n0 = blockIdx.x * 128;

    auto load_slab = [&](int st, int kele) {
        const u32 stb = smem_base + st * STAGE_BYTES;
#pragma unroll
        for (int e = tid; e < 2048; e += 256) {
            const int arr = e >> 10;         // 0:A(x) 1:B(qw)
            const int i = e & 1023;
            const int row = i >> 3, ch = i & 7;
            const __half* base = arr ? g_qw : g_x;
            const int grow = (arr ? n0 : m0) + row;
            const __half* src = base + (size_t)grow * KDIM + kele + ch * 8;
            const u32 dst = stb + arr * ARR_BYTES + row * 144 + ch * 16;
            CP_ASYNC16(dst, src);
        }
    };

    float C[4][4][4];
#pragma unroll
    for (int i = 0; i < 4; i++)
#pragma unroll
        for (int j = 0; j < 4; j++)
#pragma unroll
            for (int r = 0; r < 4; r++) C[i][j][r] = 0.0f;

    load_slab(0, 0);  CP_COMMIT();
    load_slab(1, 64); CP_COMMIT();

    const u32 a_row = warp_m * 64 + (lane & 15);
    const u32 a_colh = ((lane >> 4) & 1) * 16;
    const u32 b_row = warp_n * 32 + (lane & 7) + ((lane & 16) >> 1);
    const u32 b_colh = ((lane >> 3) & 1) * 16;

    int stage = 0, lstage = 2;
    for (int s = 0; s < NSLAB; s++) {
        CP_WAIT1();
        __syncthreads();
        if (s + 2 < NSLAB) load_slab(lstage, (s + 2) * 64);
        CP_COMMIT();

        const u32 stb = smem_base + stage * STAGE_BYTES;
#pragma unroll
        for (int kk = 0; kk < 4; kk++) {
            const u32 k0b = kk * 32;
            u32 Bv[4][2];
#pragma unroll
            for (int np = 0; np < 2; np++) {
                const u32 badr = stb + ARR_BYTES +
                                 (b_row + np * 16) * 144 + k0b + b_colh;
                u32 r0, r1, r2, r3;
                ldmx4(r0, r1, r2, r3, badr);
                Bv[np * 2][0] = r0; Bv[np * 2][1] = r1;
                Bv[np * 2 + 1][0] = r2; Bv[np * 2 + 1][1] = r3;
            }
            u32 A[4][4];
#pragma unroll
            for (int ms = 0; ms < 4; ms++) {
                const u32 aoff = (a_row + ms * 16) * 144 + k0b + a_colh;
                ldmx4(A[ms][0], A[ms][1], A[ms][2], A[ms][3], stb + aoff);
            }
#pragma unroll
            for (int ms = 0; ms < 4; ms++)
#pragma unroll
                for (int ns = 0; ns < 4; ns++)
                    mma16816(C[ms][ns], A[ms], Bv[ns]);
        }
        stage = (stage == 2) ? 0 : stage + 1;
        lstage = (lstage == 2) ? 0 : lstage + 1;
    }

    const int which = n0 / 768;         // constant per CTA (n0 multiple of 128)
    const int r_in = lane >> 2;
    const int c_in = (lane & 3) * 2;
    const int b = m0 >> 10;
    const int nloc0 = m0 & 1023;

    if (which < 2) {
        // Q or K: direct u32 stores, [B,H,N,D]
        __half* dstbase = (which == 0) ? g_Qh : g_Kh;
        const float sc = (which == 0) ? QK_SCALE_LOG2E : 1.0f;
#pragma unroll
        for (int ms = 0; ms < 4; ms++) {
#pragma unroll
            for (int ns = 0; ns < 4; ns++) {
                const int col = n0 - which * 768 + warp_n * 32 + ns * 8 + c_in;
                const int h = col >> 6, d = col & 63;
#pragma unroll
                for (int half_ = 0; half_ < 2; half_++) {
                    const int row = m0 + warp_m * 64 + ms * 16 + r_in + half_ * 8;
                    const int n = row & 1023;
                    union { __half h[2]; u32 u; } hh;
                    hh.h[0] = __float2half(C[ms][ns][half_ * 2 + 0] * sc);
                    hh.h[1] = __float2half(C[ms][ns][half_ * 2 + 1] * sc);
                    const size_t idx = ((size_t)(b * NHEAD + h) * NSEQ + n) * DHEAD + d;
                    *(u32*)(dstbase + idx) = hh.u;
                }
            }
        }
    } else {
        // V: transpose through smem, then coalesced 16B rows to g_Vt [B,H,D,N]
        __syncthreads();   // all warps past their last smem reads
        __half* Vs = (__half*)smem_raw;   // [128 clocal][VT_STRIDE]
#pragma unroll
        for (int ms = 0; ms < 4; ms++) {
#pragma unroll
            for (int ns = 0; ns < 4; ns++) {
                const int cl = warp_n * 32 + ns * 8 + c_in;
#pragma unroll
                for (int half_ = 0; half_ < 2; half_++) {
                    const int rl = warp_m * 64 + ms * 16 + r_in + half_ * 8;
                    Vs[cl * VT_STRIDE + rl]       = __float2half(C[ms][ns][half_ * 2 + 0]);
                    Vs[(cl + 1) * VT_STRIDE + rl] = __float2half(C[ms][ns][half_ * 2 + 1]);
                }
            }
        }
        __syncthreads();
        // copy out: 128 rows (clocal) x 16 chunks of 16B
        const int hbase = (n0 - 1536) >> 6;
#pragma unroll
        for (int j = tid; j < 2048; j += 256) {
            const int cl = j >> 4, c16 = j & 15;
            const int h = hbase + (cl >> 6), d = cl & 63;
            uint4 v = *(uint4*)(Vs + cl * VT_STRIDE + c16 * 8);
            __half* dst = g_Vt + ((size_t)(b * NHEAD + h) * DHEAD + d) * NSEQ
                          + nloc0 + c16 * 8;
            *(uint4*)dst = v;
        }
    }
}

// ---------------------------------------------------------------------------
// Kernel 1b: proj GEMM, tile 128x128 (reverted: best-measured shape).
// 8 warps of 64x32, K-slab 64, single-barrier 3-stage pipeline.
// ---------------------------------------------------------------------------
__global__ __launch_bounds__(256, 2) void proj_tc_kernel(
    const float* __restrict__ bias, float* __restrict__ out)
{
    extern __shared__ char smem_raw[];
    const u32 smem_base = smem_u32(smem_raw);

    const int tid = threadIdx.x;
    const int wid = tid >> 5;
    const int lane = tid & 31;
    const int warp_m = wid >> 2;
    const int warp_n = wid & 3;
    const int m0 = blockIdx.y * 128;
    const int n0 = blockIdx.x * 128;

    auto load_slab = [&](int st, int kele) {
        const u32 stb = smem_base + st * STAGE_BYTES;
#pragma unroll
        for (int e = tid; e < 2048; e += 256) {
            const int arr = e >> 10;         // 0:A(g_O) 1:B(g_pw)
            const int i = e & 1023;
            const int row = i >> 3, ch = i & 7;
            const __half* base = arr ? g_pw : g_O;
            const int grow = (arr ? n0 : m0) + row;
            const __half* src = base + (size_t)grow * KDIM + kele + ch * 8;
            const u32 dst = stb + arr * ARR_BYTES + row * 144 + ch * 16;
            CP_ASYNC16(dst, src);
        }
    };

    float C[4][4][4];
#pragma unroll
    for (int i = 0; i < 4; i++)
#pragma unroll
        for (int j = 0; j < 4; j++)
#pragma unroll
            for (int r = 0; r < 4; r++) C[i][j][r] = 0.0f;

    load_slab(0, 0);  CP_COMMIT();
    load_slab(1, 64); CP_COMMIT();

    const u32 a_row = warp_m * 64 + (lane & 15);
    const u32 a_colh = ((lane >> 4) & 1) * 16;
    const u32 b_row = warp_n * 32 + (lane & 7) + ((lane & 16) >> 1);
    const u32 b_colh = ((lane >> 3) & 1) * 16;

    int stage = 0, lstage = 2;
    for (int s = 0; s < NSLAB; s++) {
        CP_WAIT1();
        __syncthreads();
        if (s + 2 < NSLAB) load_slab(lstage, (s + 2) * 64);
        CP_COMMIT();

        const u32 stb = smem_base + stage * STAGE_BYTES;
#pragma unroll
        for (int kk = 0; kk < 4; kk++) {
            const u32 k0b = kk * 32;
            u32 Bv[4][2];
#pragma unroll
            for (int np = 0; np < 2; np++) {
                const u32 badr = stb + ARR_BYTES +
                                 (b_row + np * 16) * 144 + k0b + b_colh;
                u32 r0, r1, r2, r3;
                ldmx4(r0, r1, r2, r3, badr);
                Bv[np * 2][0] = r0; Bv[np * 2][1] = r1;
                Bv[np * 2 + 1][0] = r2; Bv[np * 2 + 1][1] = r3;
            }
            u32 A[4][4];
#pragma unroll
            for (int ms = 0; ms < 4; ms++) {
                const u32 aoff = (a_row + ms * 16) * 144 + k0b + a_colh;
                ldmx4(A[ms][0], A[ms][1], A[ms][2], A[ms][3], stb + aoff);
            }
#pragma unroll
            for (int ms = 0; ms < 4; ms++)
#pragma unroll
                for (int ns = 0; ns < 4; ns++)
                    mma16816(C[ms][ns], A[ms], Bv[ns]);
        }
        stage = (stage == 2) ? 0 : stage + 1;
        lstage = (lstage == 2) ? 0 : lstage + 1;
    }

    const int r_in = lane >> 2;
    const int c_in = (lane & 3) * 2;
#pragma unroll
    for (int ms = 0; ms < 4; ms++) {
#pragma unroll
        for (int ns = 0; ns < 4; ns++) {
            const int col = n0 + warp_n * 32 + ns * 8 + c_in;
            const float2 bb = *(const float2*)(bias + col);
#pragma unroll
            for (int half_ = 0; half_ < 2; half_++) {
                const int row = m0 + warp_m * 64 + ms * 16 + r_in + half_ * 8;
                float2 w = make_float2(C[ms][ns][half_ * 2 + 0] + bb.x,
                                       C[ms][ns][half_ * 2 + 1] + bb.y);
                *(float2*)(out + (size_t)row * 768 + col) = w;
            }
        }
    }
}

// ---------------------------------------------------------------------------
// Kernel 2: flash attention (max-free exp2 softmax, fp32 accum).
// 8 warps/CTA, Q-tile 128, K-tile 64, single-barrier 3-stage pipeline.
// Side job: converts proj_w fp32->fp16 (one 16B chunk per thread), overlapped.
// ---------------------------------------------------------------------------
#define FA_Q      18432              // 128 rows * 144B
#define FA_ARR    9216               // 64 rows * 144B
#define FA_STAGE  18432              // 2 arrays (K, Vt)
#define FA_SMEM   (FA_Q + 3 * FA_STAGE)   // 73728
#define NT        (NSEQ / 64)        // 16

__global__ __launch_bounds__(256) void flash_attn_tc_kernel(
    const float* __restrict__ pw_f32)
{
    extern __shared__ char smem_raw[];
    const u32 S0 = smem_u32(smem_raw);

    const int tid = threadIdx.x;
    const int w = tid >> 5;
    const int lane = tid & 31;
    const int qt = blockIdx.x;        // 0..7
    const int h  = blockIdx.y;
    const int b  = blockIdx.z;
    const size_t bh = (size_t)(b * NHEAD + h);

    const __half* Qg = g_Qh + (bh * NSEQ + qt * 128) * DHEAD;
    const __half* Kg = g_Kh + bh * NSEQ * DHEAD;
    const __half* Vg = g_Vt + bh * DHEAD * NSEQ;

#pragma unroll
    for (int e = tid; e < 1024; e += 256) {
        const int r = e >> 3, ch = e & 7;
        CP_ASYNC16(S0 + r * 144 + ch * 16, Qg + r * DHEAD + ch * 8);
    }

    auto load_kv = [&](int st, int t) {
        const u32 stb = S0 + FA_Q + st * FA_STAGE;
#pragma unroll
        for (int e = tid; e < 1024; e += 256) {
            const int arr = e >> 9;          // 0:K 1:Vt
            const int i = e & 511;
            const int r = i >> 3, ch = i & 7;
            const __half* src;
            if (arr == 0) src = Kg + (size_t)(t * 64 + r) * DHEAD + ch * 8;
            else          src = Vg + (size_t)r * NSEQ + t * 64 + ch * 8;
            CP_ASYNC16(stb + arr * FA_ARR + r * 144 + ch * 16, src);
        }
    };

    load_kv(0, 0); CP_COMMIT();
    load_kv(1, 1); CP_COMMIT();

    // side job: convert proj_w (overlaps with cp.async arrivals)
    {
        const int flat = (blockIdx.z * 12 + blockIdx.y) * 8 + blockIdx.x;
        const int tg = flat * 256 + tid;
        if (tg < N_PW / 4) {
            const int i = tg * 4;
            float4 v = *(const float4*)(pw_f32 + i);
            union { __half h[4]; uint2 u; } uh;
            uh.h[0] = __float2half(v.x); uh.h[1] = __float2half(v.y);
            uh.h[2] = __float2half(v.z); uh.h[3] = __float2half(v.w);
            *(uint2*)(g_pw + i) = uh.u;
        }
    }

    float O[8][4];
#pragma unroll
    for (int i = 0; i < 8; i++)
#pragma unroll
        for (int j = 0; j < 4; j++) O[i][j] = 0.0f;
    float l0 = 0.0f, l1 = 0.0f;

    const u32 qbase = S0 + w * 16 * 144;
    const u32 a_rowoff = (lane & 15) * 144 + ((lane >> 4) & 1) * 16;
    const u32 b_rowsel = (lane & 7) + ((lane & 16) >> 1);
    const u32 b_colh = ((lane >> 3) & 1) * 16;

    int stage = 0, lstage = 2;
    for (int t = 0; t < NT; t++) {
        CP_WAIT1();
        __syncthreads();
        if (t + 2 < NT) load_kv(lstage, t + 2);
        CP_COMMIT();

        const u32 stb = S0 + FA_Q + stage * FA_STAGE;
        const u32 K_s = stb, V_s = stb + FA_ARR;

        float Sc[8][4];
#pragma unroll
        for (int j = 0; j < 8; j++)
#pragma unroll
            for (int r = 0; r < 4; r++) Sc[j][r] = 0.0f;

#pragma unroll
        for (int kk = 0; kk < 4; kk++) {
            const u32 k0b = kk * 32;
            u32 Aq[4];
            ldmx4(Aq[0], Aq[1], Aq[2], Aq[3], qbase + a_rowoff + k0b);
#pragma unroll
            for (int kb = 0; kb < 4; kb++) {
                const u32 roff = (kb * 16 + b_rowsel) * 144 + k0b + b_colh;
                u32 r0, r1, r2, r3;
                ldmx4(r0, r1, r2, r3, K_s + roff);
                u32 b0[2] = {r0, r1}, b1[2] = {r2, r3};
                mma16816(Sc[kb * 2],     Aq, b0);
                mma16816(Sc[kb * 2 + 1], Aq, b1);
            }
        }

        u32 Pp01[8], Pp23[8];
#pragma unroll
        for (int j = 0; j < 8; j++) {
            Pp01[j] = exp2_h2(Sc[j][0], Sc[j][1]);
            Pp23[j] = exp2_h2(Sc[j][2], Sc[j][3]);
            float2 f0 = __half22float2(*(__half2*)&Pp01[j]);
            float2 f1 = __half22float2(*(__half2*)&Pp23[j]);
            l0 += f0.x + f0.y;
            l1 += f1.x + f1.y;
        }

#pragma unroll
        for (int kk2 = 0; kk2 < 4; kk2++) {
            u32 PA[4] = {Pp01[2 * kk2], Pp23[2 * kk2],
                         Pp01[2 * kk2 + 1], Pp23[2 * kk2 + 1]};
            const u32 k0b = kk2 * 32;
#pragma unroll
            for (int ds = 0; ds < 4; ds++) {
                const u32 roff = (ds * 16 + b_rowsel) * 144 + k0b + b_colh;
                u32 r0, r1, r2, r3;
                ldmx4(r0, r1, r2, r3, V_s + roff);
                u32 v0[2] = {r0, r1}, v1[2] = {r2, r3};
                mma16816(O[ds * 2],     PA, v0);
                mma16816(O[ds * 2 + 1], PA, v1);
            }
        }

        stage = (stage == 2) ? 0 : stage + 1;
        lstage = (lstage == 2) ? 0 : lstage + 1;
    }

    l0 += __shfl_xor_sync(0xffffffffu, l0, 1);
    l0 += __shfl_xor_sync(0xffffffffu, l0, 2);
    l1 += __shfl_xor_sync(0xffffffffu, l1, 1);
    l1 += __shfl_xor_sync(0xffffffffu, l1, 2);
    const float inv0 = 1.0f / l0, inv1 = 1.0f / l1;

    const int r0 = lane >> 2;
    const int nrow0 = qt * 128 + w * 16 + r0;
    const int colb = h * 64 + (lane & 3) * 2;
#pragma unroll
    for (int ds = 0; ds < 8; ds++) {
        const int col = colb + ds * 8;
        __half2 h0 = __floats2half2_rn(O[ds][0] * inv0, O[ds][1] * inv0);
        __half2 h1 = __floats2half2_rn(O[ds][2] * inv1, O[ds][3] * inv1);
        const size_t i0 = (size_t)(b * NSEQ + nrow0) * CDIM + col;
        const size_t i1 = (size_t)(b * NSEQ + nrow0 + 8) * CDIM + col;
        *(__half2*)(g_O + i0) = h0;
        *(__half2*)(g_O + i1) = h1;
    }
}

// ---------------------------------------------------------------------------
extern "C" void kernel_launch(void* const* d_in, const int* in_sizes, int n_in,
                              void* d_out, int out_size)
{
    const float* x      = (const float*)d_in[0];
    const float* qkv_w  = (const float*)d_in[1];
    const float* proj_w = (const float*)d_in[2];
    const float* proj_b = (const float*)d_in[3];
    float* out = (float*)d_out;

    cudaFuncSetAttribute(qkv_tc_kernel,
                         cudaFuncAttributeMaxDynamicSharedMemorySize, SMEM_DYN);
    cudaFuncSetAttribute(proj_tc_kernel,
                         cudaFuncAttributeMaxDynamicSharedMemorySize, SMEM_DYN);
    cudaFuncSetAttribute(flash_attn_tc_kernel,
                         cudaFuncAttributeMaxDynamicSharedMemorySize, FA_SMEM);

    const int ncvt = (N_X + N_QW) / 4;
    cvt_all_kernel<<<(ncvt + 255) / 256, 256>>>(x, qkv_w);

    // QKV projection -> Q(*scale*log2e)/K [B,H,N,D], Vt [B,H,D,N]
    qkv_tc_kernel<<<dim3(2304 / 128, MROWS / 128), 256, SMEM_DYN>>>();

    // Flash attention (+ pw conversion side job)
    flash_attn_tc_kernel<<<dim3(NSEQ / 128, NHEAD, BATCH), 256, FA_SMEM>>>(proj_w);

    // Output projection (+bias) -> d_out, 128x128 tiles
    proj_tc_kernel<<<dim3(768 / 128, MROWS / 128), 256, SMEM_DYN>>>(proj_b, out);
}

// round 14
// speedup vs baseline: 1.0561x; 1.0094x over previous
#include <cuda_runtime.h>
#include <cuda_fp16.h>
#include <cstdint>
#include <math.h>

#define BATCH 8
#define NSEQ  1024
#define CDIM  768
#define NHEAD 12
#define DHEAD 64
#define MROWS 8192
#define KDIM  768
// Q pre-scale: 1/sqrt(64) * log2(e)  (attention exp done as exp2)
#define QK_SCALE_LOG2E 0.18033688011112042f

typedef unsigned long long u64;
typedef unsigned int u32;

// ---------------------------------------------------------------------------
// scratch globals (allocation-free) — all single fp16
// ---------------------------------------------------------------------------
__device__ __half g_x[MROWS * CDIM];
__device__ __half g_qw[3 * CDIM * CDIM];
__device__ __half g_pw[CDIM * CDIM];
__device__ __half g_Qh[BATCH * NHEAD * NSEQ * DHEAD];  // pre-scaled by SCALE*log2e
__device__ __half g_Kh[BATCH * NHEAD * NSEQ * DHEAD];
__device__ __half g_Vt[BATCH * NHEAD * DHEAD * NSEQ];  // [B,H,D,N]
__device__ __half g_O[MROWS * CDIM];                   // attn out [B,N,C]

// ---------------------------------------------------------------------------
// PTX helpers — sm_80-era instruction set (valid under compute_103)
// ---------------------------------------------------------------------------
__device__ __forceinline__ u32 smem_u32(const void* p) {
    u32 a;
    asm("{ .reg .u64 t; cvta.to.shared.u64 t, %1; cvt.u32.u64 %0, t; }"
        : "=r"(a) : "l"(p));
    return a;
}

#define CP_ASYNC16(dst, src) \
    asm volatile("cp.async.cg.shared.global [%0], [%1], 16;" \
        :: "r"(dst), "l"(src) : "memory")
#define CP_COMMIT() asm volatile("cp.async.commit_group;" ::: "memory")
#define CP_WAIT1()  asm volatile("cp.async.wait_group 1;" ::: "memory")
#define CP_WAIT0()  asm volatile("cp.async.wait_group 0;" ::: "memory")

__device__ __forceinline__ void ldmx4(u32& r0, u32& r1, u32& r2, u32& r3, u32 addr) {
    asm volatile("ldmatrix.sync.aligned.m8n8.x4.shared.b16 {%0,%1,%2,%3}, [%4];"
        : "=r"(r0), "=r"(r1), "=r"(r2), "=r"(r3) : "r"(addr));
}

__device__ __forceinline__ void mma16816(float* c, const u32* a, const u32* b) {
    asm volatile(
        "mma.sync.aligned.m16n8k16.row.col.f32.f16.f16.f32 "
        "{%0,%1,%2,%3}, {%4,%5,%6,%7}, {%8,%9}, {%0,%1,%2,%3};"
        : "+f"(c[0]), "+f"(c[1]), "+f"(c[2]), "+f"(c[3])
        : "r"(a[0]), "r"(a[1]), "r"(a[2]), "r"(a[3]), "r"(b[0]), "r"(b[1]));
}

// exp2 of a float pair via fp16x2; returns packed half2 bits
__device__ __forceinline__ u32 exp2_h2(float a, float b) {
    __half2 h = __floats2half2_rn(a, b);
    __half2 e = h2exp2(h);
    return *(u32*)&e;
}

// ---------------------------------------------------------------------------
// Kernel 0: fused fp32 -> fp16 round for x and qkv_w (pw handled in attn)
// ---------------------------------------------------------------------------
#define N_X  (MROWS * CDIM)
#define N_QW (3 * CDIM * CDIM)
#define N_PW (CDIM * CDIM)

__global__ __launch_bounds__(256) void cvt_all_kernel(
    const float* __restrict__ x, const float* __restrict__ qw)
{
    int i = (blockIdx.x * 256 + threadIdx.x) * 4;
    const float* src;
    __half* dst;
    if (i < N_X)             { src = x + i;          dst = g_x + i; }
    else if (i < N_X + N_QW) { src = qw + (i - N_X); dst = g_qw + (i - N_X); }
    else return;
    float4 v = *(const float4*)src;
    union { __half h[4]; uint2 u; } uh;
    uh.h[0] = __float2half(v.x); uh.h[1] = __float2half(v.y);
    uh.h[2] = __float2half(v.z); uh.h[3] = __float2half(v.w);
    *(uint2*)dst = uh.u;
}

// ---------------------------------------------------------------------------
// Kernel 1: QKV GEMM (mma.sync fp16, fp32 accum).
// Block 128x128, 8 warps of 64x32, K-slab 64, single-barrier 3-stage pipeline.
// Epilogue: Q(*scale*log2e)/K -> [B,H,N,D] u32 stores; V -> smem transpose,
// then coalesced 16B rows into g_Vt [B,H,D,N].
// ---------------------------------------------------------------------------
#define ARR_BYTES   18432           // 128 * 144
#define STAGE_BYTES 36864           // 2 arrays
#define SMEM_DYN    110592          // 3 stages
#define NSLAB       12              // 768 / 64
#define VT_STRIDE   136             // halves per smem row (128 + 8 pad)

__global__ __launch_bounds__(256, 2) void qkv_tc_kernel()
{
    extern __shared__ char smem_raw[];
    const u32 smem_base = smem_u32(smem_raw);

    const int tid = threadIdx.x;
    const int wid = tid >> 5;
    const int lane = tid & 31;
    const int warp_m = wid >> 2;
    const int warp_n = wid & 3;
    const int m0 = blockIdx.y * 128;
    const int n0 = blockIdx.x * 128;

    auto load_slab = [&](int st, int kele) {
        const u32 stb = smem_base + st * STAGE_BYTES;
#pragma unroll
        for (int e = tid; e < 2048; e += 256) {
            const int arr = e >> 10;         // 0:A(x) 1:B(qw)
            const int i = e & 1023;
            const int row = i >> 3, ch = i & 7;
            const __half* base = arr ? g_qw : g_x;
            const int grow = (arr ? n0 : m0) + row;
            const __half* src = base + (size_t)grow * KDIM + kele + ch * 8;
            const u32 dst = stb + arr * ARR_BYTES + row * 144 + ch * 16;
            CP_ASYNC16(dst, src);
        }
    };

    float C[4][4][4];
#pragma unroll
    for (int i = 0; i < 4; i++)
#pragma unroll
        for (int j = 0; j < 4; j++)
#pragma unroll
            for (int r = 0; r < 4; r++) C[i][j][r] = 0.0f;

    load_slab(0, 0);  CP_COMMIT();
    load_slab(1, 64); CP_COMMIT();

    const u32 a_row = warp_m * 64 + (lane & 15);
    const u32 a_colh = ((lane >> 4) & 1) * 16;
    const u32 b_row = warp_n * 32 + (lane & 7) + ((lane & 16) >> 1);
    const u32 b_colh = ((lane >> 3) & 1) * 16;

    int stage = 0, lstage = 2;
    for (int s = 0; s < NSLAB; s++) {
        CP_WAIT1();
        __syncthreads();
        if (s + 2 < NSLAB) load_slab(lstage, (s + 2) * 64);
        CP_COMMIT();

        const u32 stb = smem_base + stage * STAGE_BYTES;
#pragma unroll
        for (int kk = 0; kk < 4; kk++) {
            const u32 k0b = kk * 32;
            u32 Bv[4][2];
#pragma unroll
            for (int np = 0; np < 2; np++) {
                const u32 badr = stb + ARR_BYTES +
                                 (b_row + np * 16) * 144 + k0b + b_colh;
                u32 r0, r1, r2, r3;
                ldmx4(r0, r1, r2, r3, badr);
                Bv[np * 2][0] = r0; Bv[np * 2][1] = r1;
                Bv[np * 2 + 1][0] = r2; Bv[np * 2 + 1][1] = r3;
            }
            u32 A[4][4];
#pragma unroll
            for (int ms = 0; ms < 4; ms++) {
                const u32 aoff = (a_row + ms * 16) * 144 + k0b + a_colh;
                ldmx4(A[ms][0], A[ms][1], A[ms][2], A[ms][3], stb + aoff);
            }
#pragma unroll
            for (int ms = 0; ms < 4; ms++)
#pragma unroll
                for (int ns = 0; ns < 4; ns++)
                    mma16816(C[ms][ns], A[ms], Bv[ns]);
        }
        stage = (stage == 2) ? 0 : stage + 1;
        lstage = (lstage == 2) ? 0 : lstage + 1;
    }

    const int which = n0 / 768;         // constant per CTA (n0 multiple of 128)
    const int r_in = lane >> 2;
    const int c_in = (lane & 3) * 2;
    const int b = m0 >> 10;
    const int nloc0 = m0 & 1023;

    if (which < 2) {
        // Q or K: direct u32 stores, [B,H,N,D]
        __half* dstbase = (which == 0) ? g_Qh : g_Kh;
        const float sc = (which == 0) ? QK_SCALE_LOG2E : 1.0f;
#pragma unroll
        for (int ms = 0; ms < 4; ms++) {
#pragma unroll
            for (int ns = 0; ns < 4; ns++) {
                const int col = n0 - which * 768 + warp_n * 32 + ns * 8 + c_in;
                const int h = col >> 6, d = col & 63;
#pragma unroll
                for (int half_ = 0; half_ < 2; half_++) {
                    const int row = m0 + warp_m * 64 + ms * 16 + r_in + half_ * 8;
                    const int n = row & 1023;
                    union { __half h[2]; u32 u; } hh;
                    hh.h[0] = __float2half(C[ms][ns][half_ * 2 + 0] * sc);
                    hh.h[1] = __float2half(C[ms][ns][half_ * 2 + 1] * sc);
                    const size_t idx = ((size_t)(b * NHEAD + h) * NSEQ + n) * DHEAD + d;
                    *(u32*)(dstbase + idx) = hh.u;
                }
            }
        }
    } else {
        // V: transpose through smem, then coalesced 16B rows to g_Vt [B,H,D,N]
        __syncthreads();   // all warps past their last smem reads
        __half* Vs = (__half*)smem_raw;   // [128 clocal][VT_STRIDE]
#pragma unroll
        for (int ms = 0; ms < 4; ms++) {
#pragma unroll
            for (int ns = 0; ns < 4; ns++) {
                const int cl = warp_n * 32 + ns * 8 + c_in;
#pragma unroll
                for (int half_ = 0; half_ < 2; half_++) {
                    const int rl = warp_m * 64 + ms * 16 + r_in + half_ * 8;
                    Vs[cl * VT_STRIDE + rl]       = __float2half(C[ms][ns][half_ * 2 + 0]);
                    Vs[(cl + 1) * VT_STRIDE + rl] = __float2half(C[ms][ns][half_ * 2 + 1]);
                }
            }
        }
        __syncthreads();
        // copy out: 128 rows (clocal) x 16 chunks of 16B
        const int hbase = (n0 - 1536) >> 6;
#pragma unroll
        for (int j = tid; j < 2048; j += 256) {
            const int cl = j >> 4, c16 = j & 15;
            const int h = hbase + (cl >> 6), d = cl & 63;
            uint4 v = *(uint4*)(Vs + cl * VT_STRIDE + c16 * 8);
            __half* dst = g_Vt + ((size_t)(b * NHEAD + h) * DHEAD + d) * NSEQ
                          + nloc0 + c16 * 8;
            *(uint4*)dst = v;
        }
    }
}

// ---------------------------------------------------------------------------
// Kernel 1b: proj GEMM, tile 128x128.  8 warps of 64x32, K-slab 64,
// single-barrier 3-stage pipeline.
// ---------------------------------------------------------------------------
__global__ __launch_bounds__(256, 2) void proj_tc_kernel(
    const float* __restrict__ bias, float* __restrict__ out)
{
    extern __shared__ char smem_raw[];
    const u32 smem_base = smem_u32(smem_raw);

    const int tid = threadIdx.x;
    const int wid = tid >> 5;
    const int lane = tid & 31;
    const int warp_m = wid >> 2;
    const int warp_n = wid & 3;
    const int m0 = blockIdx.y * 128;
    const int n0 = blockIdx.x * 128;

    auto load_slab = [&](int st, int kele) {
        const u32 stb = smem_base + st * STAGE_BYTES;
#pragma unroll
        for (int e = tid; e < 2048; e += 256) {
            const int arr = e >> 10;         // 0:A(g_O) 1:B(g_pw)
            const int i = e & 1023;
            const int row = i >> 3, ch = i & 7;
            const __half* base = arr ? g_pw : g_O;
            const int grow = (arr ? n0 : m0) + row;
            const __half* src = base + (size_t)grow * KDIM + kele + ch * 8;
            const u32 dst = stb + arr * ARR_BYTES + row * 144 + ch * 16;
            CP_ASYNC16(dst, src);
        }
    };

    float C[4][4][4];
#pragma unroll
    for (int i = 0; i < 4; i++)
#pragma unroll
        for (int j = 0; j < 4; j++)
#pragma unroll
            for (int r = 0; r < 4; r++) C[i][j][r] = 0.0f;

    load_slab(0, 0);  CP_COMMIT();
    load_slab(1, 64); CP_COMMIT();

    const u32 a_row = warp_m * 64 + (lane & 15);
    const u32 a_colh = ((lane >> 4) & 1) * 16;
    const u32 b_row = warp_n * 32 + (lane & 7) + ((lane & 16) >> 1);
    const u32 b_colh = ((lane >> 3) & 1) * 16;

    int stage = 0, lstage = 2;
    for (int s = 0; s < NSLAB; s++) {
        CP_WAIT1();
        __syncthreads();
        if (s + 2 < NSLAB) load_slab(lstage, (s + 2) * 64);
        CP_COMMIT();

        const u32 stb = smem_base + stage * STAGE_BYTES;
#pragma unroll
        for (int kk = 0; kk < 4; kk++) {
            const u32 k0b = kk * 32;
            u32 Bv[4][2];
#pragma unroll
            for (int np = 0; np < 2; np++) {
                const u32 badr = stb + ARR_BYTES +
                                 (b_row + np * 16) * 144 + k0b + b_colh;
                u32 r0, r1, r2, r3;
                ldmx4(r0, r1, r2, r3, badr);
                Bv[np * 2][0] = r0; Bv[np * 2][1] = r1;
                Bv[np * 2 + 1][0] = r2; Bv[np * 2 + 1][1] = r3;
            }
            u32 A[4][4];
#pragma unroll
            for (int ms = 0; ms < 4; ms++) {
                const u32 aoff = (a_row + ms * 16) * 144 + k0b + a_colh;
                ldmx4(A[ms][0], A[ms][1], A[ms][2], A[ms][3], stb + aoff);
            }
#pragma unroll
            for (int ms = 0; ms < 4; ms++)
#pragma unroll
                for (int ns = 0; ns < 4; ns++)
                    mma16816(C[ms][ns], A[ms], Bv[ns]);
        }
        stage = (stage == 2) ? 0 : stage + 1;
        lstage = (lstage == 2) ? 0 : lstage + 1;
    }

    const int r_in = lane >> 2;
    const int c_in = (lane & 3) * 2;
#pragma unroll
    for (int ms = 0; ms < 4; ms++) {
#pragma unroll
        for (int ns = 0; ns < 4; ns++) {
            const int col = n0 + warp_n * 32 + ns * 8 + c_in;
            const float2 bb = *(const float2*)(bias + col);
#pragma unroll
            for (int half_ = 0; half_ < 2; half_++) {
                const int row = m0 + warp_m * 64 + ms * 16 + r_in + half_ * 8;
                float2 w = make_float2(C[ms][ns][half_ * 2 + 0] + bb.x,
                                       C[ms][ns][half_ * 2 + 1] + bb.y);
                *(float2*)(out + (size_t)row * 768 + col) = w;
            }
        }
    }
}

// ---------------------------------------------------------------------------
// Kernel 2: flash attention (max-free exp2 softmax, fp32 accum).
// 8 warps/CTA, Q-tile 128.  K-tile 128 per smem stage, processed as two
// 64-key sub-passes (register footprint unchanged).  2-stage lookahead-1
// single-barrier pipeline (8 barriers total).
// l computed by ones-fragment MMA (Cl accumulator) — no scalar sums/shuffles.
// Side job: converts proj_w fp32->fp16, overlapped with cp.async prologue.
// ---------------------------------------------------------------------------
#define FA_Q       18432             // 128 rows * 144B
#define FA_K_BYTES 18432             // 128 key rows * 144B
#define FA_V_OFF   18432             // Vt offset within stage
#define FA_V_ROW   272               // 128 keys * 2B + 16 pad
#define FA_STAGE   (FA_K_BYTES + 64 * FA_V_ROW)   // 35840
#define FA_SMEM    (FA_Q + 2 * FA_STAGE)          // 90112
#define NT2        (NSEQ / 128)      // 8

__global__ __launch_bounds__(256) void flash_attn_tc_kernel(
    const float* __restrict__ pw_f32)
{
    extern __shared__ char smem_raw[];
    const u32 S0 = smem_u32(smem_raw);

    const int tid = threadIdx.x;
    const int w = tid >> 5;
    const int lane = tid & 31;
    const int qt = blockIdx.x;        // 0..7
    const int h  = blockIdx.y;
    const int b  = blockIdx.z;
    const size_t bh = (size_t)(b * NHEAD + h);

    const __half* Qg = g_Qh + (bh * NSEQ + qt * 128) * DHEAD;
    const __half* Kg = g_Kh + bh * NSEQ * DHEAD;
    const __half* Vg = g_Vt + bh * DHEAD * NSEQ;

    // Q tile: 128 rows x 8 chunks of 16B (commit group 0, with kv tile 0)
#pragma unroll
    for (int e = tid; e < 1024; e += 256) {
        const int r = e >> 3, ch = e & 7;
        CP_ASYNC16(S0 + r * 144 + ch * 16, Qg + r * DHEAD + ch * 8);
    }

    // 128-key tile: K 128x(64h) rows + Vt 64x(128h) rows
    auto load_kv = [&](int st, int tt) {
        const u32 stb = S0 + FA_Q + st * FA_STAGE;
#pragma unroll
        for (int e = tid; e < 2048; e += 256) {
            if (e < 1024) {
                const int r = e >> 3, ch = e & 7;
                CP_ASYNC16(stb + r * 144 + ch * 16,
                           Kg + (size_t)(tt * 128 + r) * DHEAD + ch * 8);
            } else {
                const int i = e - 1024;
                const int d = i >> 4, ch = i & 15;
                CP_ASYNC16(stb + FA_V_OFF + d * FA_V_ROW + ch * 16,
                           Vg + (size_t)d * NSEQ + tt * 128 + ch * 8);
            }
        }
    };

    load_kv(0, 0); CP_COMMIT();

    // side job: convert proj_w (overlaps with cp.async arrivals)
    {
        const int flat = (blockIdx.z * 12 + blockIdx.y) * 8 + blockIdx.x;
        const int tg = flat * 256 + tid;
        if (tg < N_PW / 4) {
            const int i = tg * 4;
            float4 v = *(const float4*)(pw_f32 + i);
            union { __half h[4]; uint2 u; } uh;
            uh.h[0] = __float2half(v.x); uh.h[1] = __float2half(v.y);
            uh.h[2] = __float2half(v.z); uh.h[3] = __float2half(v.w);
            *(uint2*)(g_pw + i) = uh.u;
        }
    }

    float O[8][4];
#pragma unroll
    for (int i = 0; i < 8; i++)
#pragma unroll
        for (int j = 0; j < 4; j++) O[i][j] = 0.0f;
    float Cl[4] = {0.0f, 0.0f, 0.0f, 0.0f};      // l via ones-MMA

    const u32 ones_frag[2] = {0x3C003C00u, 0x3C003C00u};   // fp16 1.0 x4

    const u32 qbase = S0 + w * 16 * 144;
    const u32 a_rowoff = (lane & 15) * 144 + ((lane >> 4) & 1) * 16;
    const u32 b_rowsel = (lane & 7) + ((lane & 16) >> 1);
    const u32 b_colh = ((lane >> 3) & 1) * 16;

    for (int t = 0; t < NT2; t++) {
        CP_WAIT0();
        __syncthreads();
        // refill the stage consumed at iteration t-1 (WAR-safe after barrier)
        if (t + 1 < NT2) load_kv((t + 1) & 1, t + 1);
        CP_COMMIT();

        const u32 stb = S0 + FA_Q + (t & 1) * FA_STAGE;

#pragma unroll
        for (int sub = 0; sub < 2; sub++) {
            const u32 K_s = stb + sub * 64 * 144;
            const u32 V_s = stb + FA_V_OFF;
            const u32 v_sub = sub * 128;       // byte offset within Vt row

            // ---- S = Q K^T (16x64 per warp), log2 domain ----
            float Sc[8][4];
#pragma unroll
            for (int j = 0; j < 8; j++)
#pragma unroll
                for (int r = 0; r < 4; r++) Sc[j][r] = 0.0f;

#pragma unroll
            for (int kk = 0; kk < 4; kk++) {
                const u32 k0b = kk * 32;
                u32 Aq[4];
                ldmx4(Aq[0], Aq[1], Aq[2], Aq[3], qbase + a_rowoff + k0b);
#pragma unroll
                for (int kb = 0; kb < 4; kb++) {
                    const u32 roff = (kb * 16 + b_rowsel) * 144 + k0b + b_colh;
                    u32 r0, r1, r2, r3;
                    ldmx4(r0, r1, r2, r3, K_s + roff);
                    u32 b0[2] = {r0, r1}, b1[2] = {r2, r3};
                    mma16816(Sc[kb * 2],     Aq, b0);
                    mma16816(Sc[kb * 2 + 1], Aq, b1);
                }
            }

            // ---- P = exp2(S) in fp16 pairs ----
            u32 Pp01[8], Pp23[8];
#pragma unroll
            for (int j = 0; j < 8; j++) {
                Pp01[j] = exp2_h2(Sc[j][0], Sc[j][1]);
                Pp23[j] = exp2_h2(Sc[j][2], Sc[j][3]);
            }

            // ---- O += P V ; l += P x ones (16x64 per warp) ----
#pragma unroll
            for (int kk2 = 0; kk2 < 4; kk2++) {
                u32 PA[4] = {Pp01[2 * kk2], Pp23[2 * kk2],
                             Pp01[2 * kk2 + 1], Pp23[2 * kk2 + 1]};
                const u32 k0b = kk2 * 32;
#pragma unroll
                for (int ds = 0; ds < 4; ds++) {
                    const u32 roff = (ds * 16 + b_rowsel) * FA_V_ROW + v_sub + k0b + b_colh;
                    u32 r0, r1, r2, r3;
                    ldmx4(r0, r1, r2, r3, V_s + roff);
                    u32 v0[2] = {r0, r1}, v1[2] = {r2, r3};
                    mma16816(O[ds * 2],     PA, v0);
                    mma16816(O[ds * 2 + 1], PA, v1);
                }
                mma16816(Cl, PA, ones_frag);
            }
        }
    }

    const float inv0 = 1.0f / Cl[0], inv1 = 1.0f / Cl[2];

    const int r0 = lane >> 2;
    const int nrow0 = qt * 128 + w * 16 + r0;
    const int colb = h * 64 + (lane & 3) * 2;
#pragma unroll
    for (int ds = 0; ds < 8; ds++) {
        const int col = colb + ds * 8;
        __half2 h0 = __floats2half2_rn(O[ds][0] * inv0, O[ds][1] * inv0);
        __half2 h1 = __floats2half2_rn(O[ds][2] * inv1, O[ds][3] * inv1);
        const size_t i0 = (size_t)(b * NSEQ + nrow0) * CDIM + col;
        const size_t i1 = (size_t)(b * NSEQ + nrow0 + 8) * CDIM + col;
        *(__half2*)(g_O + i0) = h0;
        *(__half2*)(g_O + i1) = h1;
    }
}

// ---------------------------------------------------------------------------
extern "C" void kernel_launch(void* const* d_in, const int* in_sizes, int n_in,
                              void* d_out, int out_size)
{
    const float* x      = (const float*)d_in[0];
    const float* qkv_w  = (const float*)d_in[1];
    const float* proj_w = (const float*)d_in[2];
    const float* proj_b = (const float*)d_in[3];
    float* out = (float*)d_out;

    cudaFuncSetAttribute(qkv_tc_kernel,
                         cudaFuncAttributeMaxDynamicSharedMemorySize, SMEM_DYN);
    cudaFuncSetAttribute(proj_tc_kernel,
                         cudaFuncAttributeMaxDynamicSharedMemorySize, SMEM_DYN);
    cudaFuncSetAttribute(flash_attn_tc_kernel,
                         cudaFuncAttributeMaxDynamicSharedMemorySize, FA_SMEM);

    const int ncvt = (N_X + N_QW) / 4;
    cvt_all_kernel<<<(ncvt + 255) / 256, 256>>>(x, qkv_w);

    // QKV projection -> Q(*scale*log2e)/K [B,H,N,D], Vt [B,H,D,N]
    qkv_tc_kernel<<<dim3(2304 / 128, MROWS / 128), 256, SMEM_DYN>>>();

    // Flash attention (+ pw conversion side job)
    flash_attn_tc_kernel<<<dim3(NSEQ / 128, NHEAD, BATCH), 256, FA_SMEM>>>(proj_w);

    // Output projection (+bias) -> d_out, 128x128 tiles
    proj_tc_kernel<<<dim3(768 / 128, MROWS / 128), 256, SMEM_DYN>>>(proj_b, out);
}

// round 15
// speedup vs baseline: 1.1299x; 1.0699x over previous
#include <cuda_runtime.h>
#include <cuda_fp16.h>
#include <cstdint>
#include <math.h>

#define BATCH 8
#define NSEQ  1024
#define CDIM  768
#define NHEAD 12
#define DHEAD 64
#define MROWS 8192
#define KDIM  768
#define QK_SCALE_LOG2E 0.18033688011112042f

typedef unsigned long long u64;
typedef unsigned int u32;

// ---------------------------------------------------------------------------
// scratch globals (allocation-free) — all single fp16
// ---------------------------------------------------------------------------
__device__ __half g_x[MROWS * CDIM];
__device__ __half g_qw[3 * CDIM * CDIM];
__device__ __half g_pw[CDIM * CDIM];
__device__ __half g_Qh[BATCH * NHEAD * NSEQ * DHEAD];  // pre-scaled by SCALE*log2e
__device__ __half g_Kh[BATCH * NHEAD * NSEQ * DHEAD];
__device__ __half g_Vt[BATCH * NHEAD * DHEAD * NSEQ];  // [B,H,D,N]
__device__ __half g_O[MROWS * CDIM];                   // attn out [B,N,C]
__device__ int    g_ctr[64];                           // per-(b,qt) head counters

// ---------------------------------------------------------------------------
// PTX helpers — sm_80-era instruction set (valid under compute_103)
// ---------------------------------------------------------------------------
__device__ __forceinline__ u32 smem_u32(const void* p) {
    u32 a;
    asm("{ .reg .u64 t; cvta.to.shared.u64 t, %1; cvt.u32.u64 %0, t; }"
        : "=r"(a) : "l"(p));
    return a;
}

#define CP_ASYNC16(dst, src) \
    asm volatile("cp.async.cg.shared.global [%0], [%1], 16;" \
        :: "r"(dst), "l"(src) : "memory")
#define CP_COMMIT() asm volatile("cp.async.commit_group;" ::: "memory")
#define CP_WAIT1()  asm volatile("cp.async.wait_group 1;" ::: "memory")
#define CP_WAIT0()  asm volatile("cp.async.wait_group 0;" ::: "memory")

__device__ __forceinline__ void ldmx4(u32& r0, u32& r1, u32& r2, u32& r3, u32 addr) {
    asm volatile("ldmatrix.sync.aligned.m8n8.x4.shared.b16 {%0,%1,%2,%3}, [%4];"
        : "=r"(r0), "=r"(r1), "=r"(r2), "=r"(r3) : "r"(addr));
}

__device__ __forceinline__ void mma16816(float* c, const u32* a, const u32* b) {
    asm volatile(
        "mma.sync.aligned.m16n8k16.row.col.f32.f16.f16.f32 "
        "{%0,%1,%2,%3}, {%4,%5,%6,%7}, {%8,%9}, {%0,%1,%2,%3};"
        : "+f"(c[0]), "+f"(c[1]), "+f"(c[2]), "+f"(c[3])
        : "r"(a[0]), "r"(a[1]), "r"(a[2]), "r"(a[3]), "r"(b[0]), "r"(b[1]));
}

__device__ __forceinline__ u32 exp2_h2(float a, float b) {
    __half2 h = __floats2half2_rn(a, b);
    __half2 e = h2exp2(h);
    return *(u32*)&e;
}

// ---------------------------------------------------------------------------
// Kernel 0: fp32 -> fp16 for x, qkv_w, proj_w; also zeroes the dep counters.
// ---------------------------------------------------------------------------
#define N_X  (MROWS * CDIM)
#define N_QW (3 * CDIM * CDIM)
#define N_PW (CDIM * CDIM)

__global__ __launch_bounds__(256) void cvt_all_kernel(
    const float* __restrict__ x, const float* __restrict__ qw,
    const float* __restrict__ pw)
{
    if (blockIdx.x == 0 && threadIdx.x < 64) g_ctr[threadIdx.x] = 0;
    int i = (blockIdx.x * 256 + threadIdx.x) * 4;
    const float* src;
    __half* dst;
    if (i < N_X)                    { src = x + i;                dst = g_x + i; }
    else if (i < N_X + N_QW)        { src = qw + (i - N_X);       dst = g_qw + (i - N_X); }
    else if (i < N_X + N_QW + N_PW) { src = pw + (i - N_X - N_QW); dst = g_pw + (i - N_X - N_QW); }
    else return;
    float4 v = *(const float4*)src;
    union { __half h[4]; uint2 u; } uh;
    uh.h[0] = __float2half(v.x); uh.h[1] = __float2half(v.y);
    uh.h[2] = __float2half(v.z); uh.h[3] = __float2half(v.w);
    *(uint2*)dst = uh.u;
}

// ---------------------------------------------------------------------------
// Kernel 1: QKV GEMM (unchanged from best-measured R14 variant)
// ---------------------------------------------------------------------------
#define ARR_BYTES   18432
#define STAGE_BYTES 36864
#define SMEM_DYN    110592
#define NSLAB       12
#define VT_STRIDE   136

__global__ __launch_bounds__(256, 2) void qkv_tc_kernel()
{
    extern __shared__ char smem_raw[];
    const u32 smem_base = smem_u32(smem_raw);

    const int tid = threadIdx.x;
    const int wid = tid >> 5;
    const int lane = tid & 31;
    const int warp_m = wid >> 2;
    const int warp_n = wid & 3;
    const int m0 = blockIdx.y * 128;
    const int n0 = blockIdx.x * 128;

    auto load_slab = [&](int st, int kele) {
        const u32 stb = smem_base + st * STAGE_BYTES;
#pragma unroll
        for (int e = tid; e < 2048; e += 256) {
            const int arr = e >> 10;
            const int i = e & 1023;
            const int row = i >> 3, ch = i & 7;
            const __half* base = arr ? g_qw : g_x;
            const int grow = (arr ? n0 : m0) + row;
            const __half* src = base + (size_t)grow * KDIM + kele + ch * 8;
            const u32 dst = stb + arr * ARR_BYTES + row * 144 + ch * 16;
            CP_ASYNC16(dst, src);
        }
    };

    float C[4][4][4];
#pragma unroll
    for (int i = 0; i < 4; i++)
#pragma unroll
        for (int j = 0; j < 4; j++)
#pragma unroll
            for (int r = 0; r < 4; r++) C[i][j][r] = 0.0f;

    load_slab(0, 0);  CP_COMMIT();
    load_slab(1, 64); CP_COMMIT();

    const u32 a_row = warp_m * 64 + (lane & 15);
    const u32 a_colh = ((lane >> 4) & 1) * 16;
    const u32 b_row = warp_n * 32 + (lane & 7) + ((lane & 16) >> 1);
    const u32 b_colh = ((lane >> 3) & 1) * 16;

    int stage = 0, lstage = 2;
    for (int s = 0; s < NSLAB; s++) {
        CP_WAIT1();
        __syncthreads();
        if (s + 2 < NSLAB) load_slab(lstage, (s + 2) * 64);
        CP_COMMIT();

        const u32 stb = smem_base + stage * STAGE_BYTES;
#pragma unroll
        for (int kk = 0; kk < 4; kk++) {
            const u32 k0b = kk * 32;
            u32 Bv[4][2];
#pragma unroll
            for (int np = 0; np < 2; np++) {
                const u32 badr = stb + ARR_BYTES +
                                 (b_row + np * 16) * 144 + k0b + b_colh;
                u32 r0, r1, r2, r3;
                ldmx4(r0, r1, r2, r3, badr);
                Bv[np * 2][0] = r0; Bv[np * 2][1] = r1;
                Bv[np * 2 + 1][0] = r2; Bv[np * 2 + 1][1] = r3;
            }
            u32 A[4][4];
#pragma unroll
            for (int ms = 0; ms < 4; ms++) {
                const u32 aoff = (a_row + ms * 16) * 144 + k0b + a_colh;
                ldmx4(A[ms][0], A[ms][1], A[ms][2], A[ms][3], stb + aoff);
            }
#pragma unroll
            for (int ms = 0; ms < 4; ms++)
#pragma unroll
                for (int ns = 0; ns < 4; ns++)
                    mma16816(C[ms][ns], A[ms], Bv[ns]);
        }
        stage = (stage == 2) ? 0 : stage + 1;
        lstage = (lstage == 2) ? 0 : lstage + 1;
    }

    const int which = n0 / 768;
    const int r_in = lane >> 2;
    const int c_in = (lane & 3) * 2;
    const int b = m0 >> 10;
    const int nloc0 = m0 & 1023;

    if (which < 2) {
        __half* dstbase = (which == 0) ? g_Qh : g_Kh;
        const float sc = (which == 0) ? QK_SCALE_LOG2E : 1.0f;
#pragma unroll
        for (int ms = 0; ms < 4; ms++) {
#pragma unroll
            for (int ns = 0; ns < 4; ns++) {
                const int col = n0 - which * 768 + warp_n * 32 + ns * 8 + c_in;
                const int h = col >> 6, d = col & 63;
#pragma unroll
                for (int half_ = 0; half_ < 2; half_++) {
                    const int row = m0 + warp_m * 64 + ms * 16 + r_in + half_ * 8;
                    const int n = row & 1023;
                    union { __half h[2]; u32 u; } hh;
                    hh.h[0] = __float2half(C[ms][ns][half_ * 2 + 0] * sc);
                    hh.h[1] = __float2half(C[ms][ns][half_ * 2 + 1] * sc);
                    const size_t idx = ((size_t)(b * NHEAD + h) * NSEQ + n) * DHEAD + d;
                    *(u32*)(dstbase + idx) = hh.u;
                }
            }
        }
    } else {
        __syncthreads();
        __half* Vs = (__half*)smem_raw;
#pragma unroll
        for (int ms = 0; ms < 4; ms++) {
#pragma unroll
            for (int ns = 0; ns < 4; ns++) {
                const int cl = warp_n * 32 + ns * 8 + c_in;
#pragma unroll
                for (int half_ = 0; half_ < 2; half_++) {
                    const int rl = warp_m * 64 + ms * 16 + r_in + half_ * 8;
                    Vs[cl * VT_STRIDE + rl]       = __float2half(C[ms][ns][half_ * 2 + 0]);
                    Vs[(cl + 1) * VT_STRIDE + rl] = __float2half(C[ms][ns][half_ * 2 + 1]);
                }
            }
        }
        __syncthreads();
        const int hbase = (n0 - 1536) >> 6;
#pragma unroll
        for (int j = tid; j < 2048; j += 256) {
            const int cl = j >> 4, c16 = j & 15;
            const int h = hbase + (cl >> 6), d = cl & 63;
            uint4 v = *(uint4*)(Vs + cl * VT_STRIDE + c16 * 8);
            __half* dst = g_Vt + ((size_t)(b * NHEAD + h) * DHEAD + d) * NSEQ
                          + nloc0 + c16 * 8;
            *(uint4*)dst = v;
        }
    }
}

// ---------------------------------------------------------------------------
// Kernel 2: FUSED attention + output projection, one launch of 1152 blocks.
//   blocks [0,768):    flash attention (R14 structure) + counter release
//   blocks [768,1152): proj 128x128 tiles, spin-wait on per-(b,qt) counter
// Deadlock-free: blocks dispatch in bid order, so every attention block is
// resident/finished before any proj block occupies a slot.
// ---------------------------------------------------------------------------
#define FA_Q       18432
#define FA_K_BYTES 18432
#define FA_V_OFF   18432
#define FA_V_ROW   272
#define FA_STAGE   (FA_K_BYTES + 64 * FA_V_ROW)   // 35840
#define FA_SMEM    (FA_Q + 2 * FA_STAGE)          // 90112  (>= proj's 73728)
#define NT2        (NSEQ / 128)                   // 8

__global__ __launch_bounds__(256, 2) void attn_proj_kernel(
    const float* __restrict__ bias, float* __restrict__ out)
{
    extern __shared__ char smem_raw[];
    const u32 S0 = smem_u32(smem_raw);
    const int tid = threadIdx.x;
    const int wid = tid >> 5;
    const int lane = tid & 31;
    const int bid = blockIdx.x;

    if (bid < 768) {
        // ================= ATTENTION =================
        const int qt = bid & 7;
        const int h  = (bid >> 3) % 12;
        const int b  = bid / 96;
        const int w = wid;
        const size_t bh = (size_t)(b * NHEAD + h);

        const __half* Qg = g_Qh + (bh * NSEQ + qt * 128) * DHEAD;
        const __half* Kg = g_Kh + bh * NSEQ * DHEAD;
        const __half* Vg = g_Vt + bh * DHEAD * NSEQ;

#pragma unroll
        for (int e = tid; e < 1024; e += 256) {
            const int r = e >> 3, ch = e & 7;
            CP_ASYNC16(S0 + r * 144 + ch * 16, Qg + r * DHEAD + ch * 8);
        }

        auto load_kv = [&](int st, int tt) {
            const u32 stb = S0 + FA_Q + st * FA_STAGE;
#pragma unroll
            for (int e = tid; e < 2048; e += 256) {
                if (e < 1024) {
                    const int r = e >> 3, ch = e & 7;
                    CP_ASYNC16(stb + r * 144 + ch * 16,
                               Kg + (size_t)(tt * 128 + r) * DHEAD + ch * 8);
                } else {
                    const int i = e - 1024;
                    const int d = i >> 4, ch = i & 15;
                    CP_ASYNC16(stb + FA_V_OFF + d * FA_V_ROW + ch * 16,
                               Vg + (size_t)d * NSEQ + tt * 128 + ch * 8);
                }
            }
        };

        load_kv(0, 0); CP_COMMIT();

        float O[8][4];
#pragma unroll
        for (int i = 0; i < 8; i++)
#pragma unroll
            for (int j = 0; j < 4; j++) O[i][j] = 0.0f;
        float Cl[4] = {0.0f, 0.0f, 0.0f, 0.0f};
        const u32 ones_frag[2] = {0x3C003C00u, 0x3C003C00u};

        const u32 qbase = S0 + w * 16 * 144;
        const u32 a_rowoff = (lane & 15) * 144 + ((lane >> 4) & 1) * 16;
        const u32 b_rowsel = (lane & 7) + ((lane & 16) >> 1);
        const u32 b_colh = ((lane >> 3) & 1) * 16;

        for (int t = 0; t < NT2; t++) {
            CP_WAIT0();
            __syncthreads();
            if (t + 1 < NT2) load_kv((t + 1) & 1, t + 1);
            CP_COMMIT();

            const u32 stb = S0 + FA_Q + (t & 1) * FA_STAGE;

#pragma unroll
            for (int sub = 0; sub < 2; sub++) {
                const u32 K_s = stb + sub * 64 * 144;
                const u32 V_s = stb + FA_V_OFF;
                const u32 v_sub = sub * 128;

                float Sc[8][4];
#pragma unroll
                for (int j = 0; j < 8; j++)
#pragma unroll
                    for (int r = 0; r < 4; r++) Sc[j][r] = 0.0f;

#pragma unroll
                for (int kk = 0; kk < 4; kk++) {
                    const u32 k0b = kk * 32;
                    u32 Aq[4];
                    ldmx4(Aq[0], Aq[1], Aq[2], Aq[3], qbase + a_rowoff + k0b);
#pragma unroll
                    for (int kb = 0; kb < 4; kb++) {
                        const u32 roff = (kb * 16 + b_rowsel) * 144 + k0b + b_colh;
                        u32 r0, r1, r2, r3;
                        ldmx4(r0, r1, r2, r3, K_s + roff);
                        u32 b0[2] = {r0, r1}, b1[2] = {r2, r3};
                        mma16816(Sc[kb * 2],     Aq, b0);
                        mma16816(Sc[kb * 2 + 1], Aq, b1);
                    }
                }

                u32 Pp01[8], Pp23[8];
#pragma unroll
                for (int j = 0; j < 8; j++) {
                    Pp01[j] = exp2_h2(Sc[j][0], Sc[j][1]);
                    Pp23[j] = exp2_h2(Sc[j][2], Sc[j][3]);
                }

#pragma unroll
                for (int kk2 = 0; kk2 < 4; kk2++) {
                    u32 PA[4] = {Pp01[2 * kk2], Pp23[2 * kk2],
                                 Pp01[2 * kk2 + 1], Pp23[2 * kk2 + 1]};
                    const u32 k0b = kk2 * 32;
#pragma unroll
                    for (int ds = 0; ds < 4; ds++) {
                        const u32 roff = (ds * 16 + b_rowsel) * FA_V_ROW + v_sub + k0b + b_colh;
                        u32 r0, r1, r2, r3;
                        ldmx4(r0, r1, r2, r3, V_s + roff);
                        u32 v0[2] = {r0, r1}, v1[2] = {r2, r3};
                        mma16816(O[ds * 2],     PA, v0);
                        mma16816(O[ds * 2 + 1], PA, v1);
                    }
                    mma16816(Cl, PA, ones_frag);
                }
            }
        }

        const float inv0 = 1.0f / Cl[0], inv1 = 1.0f / Cl[2];
        const int r0 = lane >> 2;
        const int nrow0 = qt * 128 + w * 16 + r0;
        const int colb = h * 64 + (lane & 3) * 2;
#pragma unroll
        for (int ds = 0; ds < 8; ds++) {
            const int col = colb + ds * 8;
            __half2 h0 = __floats2half2_rn(O[ds][0] * inv0, O[ds][1] * inv0);
            __half2 h1 = __floats2half2_rn(O[ds][2] * inv1, O[ds][3] * inv1);
            const size_t i0 = (size_t)(b * NSEQ + nrow0) * CDIM + col;
            const size_t i1 = (size_t)(b * NSEQ + nrow0 + 8) * CDIM + col;
            *(__half2*)(g_O + i0) = h0;
            *(__half2*)(g_O + i1) = h1;
        }

        // release: rows [b*NSEQ + qt*128, +128) of g_O (this head) are done
        __threadfence();
        __syncthreads();
        if (tid == 0) atomicAdd(&g_ctr[b * 8 + qt], 1);

    } else {
        // ================= PROJ (128x128 tile) =================
        const int p = bid - 768;
        const int m0 = (p / 6) * 128;
        const int n0 = (p % 6) * 128;

        // wait for all 12 heads of this (b,qt) row block
        if (tid == 0) {
            volatile int* c = (volatile int*)&g_ctr[m0 >> 7];
            while (*c < 12) { }
            __threadfence();
        }
        __syncthreads();

        auto load_slab = [&](int st, int kele) {
            const u32 stb = S0 + st * STAGE_BYTES;
#pragma unroll
            for (int e = tid; e < 2048; e += 256) {
                const int arr = e >> 10;     // 0:A(g_O) 1:B(g_pw)
                const int i = e & 1023;
                const int row = i >> 3, ch = i & 7;
                const __half* base = arr ? g_pw : g_O;
                const int grow = (arr ? n0 : m0) + row;
                const __half* src = base + (size_t)grow * KDIM + kele + ch * 8;
                const u32 dst = stb + arr * ARR_BYTES + row * 144 + ch * 16;
                CP_ASYNC16(dst, src);
            }
        };

        float C[4][4][4];
#pragma unroll
        for (int i = 0; i < 4; i++)
#pragma unroll
            for (int j = 0; j < 4; j++)
#pragma unroll
                for (int r = 0; r < 4; r++) C[i][j][r] = 0.0f;

        load_slab(0, 0); CP_COMMIT();

        const int warp_m = wid >> 2;
        const int warp_n = wid & 3;
        const u32 a_row = warp_m * 64 + (lane & 15);
        const u32 a_colh = ((lane >> 4) & 1) * 16;
        const u32 b_row = warp_n * 32 + (lane & 7) + ((lane & 16) >> 1);
        const u32 b_colh = ((lane >> 3) & 1) * 16;

        for (int s = 0; s < NSLAB; s++) {
            CP_WAIT0();
            __syncthreads();
            if (s + 1 < NSLAB) load_slab((s + 1) & 1, (s + 1) * 64);
            CP_COMMIT();

            const u32 stb = S0 + (s & 1) * STAGE_BYTES;
#pragma unroll
            for (int kk = 0; kk < 4; kk++) {
                const u32 k0b = kk * 32;
                u32 Bv[4][2];
#pragma unroll
                for (int np = 0; np < 2; np++) {
                    const u32 badr = stb + ARR_BYTES +
                                     (b_row + np * 16) * 144 + k0b + b_colh;
                    u32 r0, r1, r2, r3;
                    ldmx4(r0, r1, r2, r3, badr);
                    Bv[np * 2][0] = r0; Bv[np * 2][1] = r1;
                    Bv[np * 2 + 1][0] = r2; Bv[np * 2 + 1][1] = r3;
                }
                u32 A[4][4];
#pragma unroll
                for (int ms = 0; ms < 4; ms++) {
                    const u32 aoff = (a_row + ms * 16) * 144 + k0b + a_colh;
                    ldmx4(A[ms][0], A[ms][1], A[ms][2], A[ms][3], stb + aoff);
                }
#pragma unroll
                for (int ms = 0; ms < 4; ms++)
#pragma unroll
                    for (int ns = 0; ns < 4; ns++)
                        mma16816(C[ms][ns], A[ms], Bv[ns]);
            }
        }

        const int r_in = lane >> 2;
        const int c_in = (lane & 3) * 2;
#pragma unroll
        for (int ms = 0; ms < 4; ms++) {
#pragma unroll
            for (int ns = 0; ns < 4; ns++) {
                const int col = n0 + warp_n * 32 + ns * 8 + c_in;
                const float2 bb = *(const float2*)(bias + col);
#pragma unroll
                for (int half_ = 0; half_ < 2; half_++) {
                    const int row = m0 + warp_m * 64 + ms * 16 + r_in + half_ * 8;
                    float2 w2 = make_float2(C[ms][ns][half_ * 2 + 0] + bb.x,
                                            C[ms][ns][half_ * 2 + 1] + bb.y);
                    *(float2*)(out + (size_t)row * 768 + col) = w2;
                }
            }
        }
    }
}

// ---------------------------------------------------------------------------
extern "C" void kernel_launch(void* const* d_in, const int* in_sizes, int n_in,
                              void* d_out, int out_size)
{
    const float* x      = (const float*)d_in[0];
    const float* qkv_w  = (const float*)d_in[1];
    const float* proj_w = (const float*)d_in[2];
    const float* proj_b = (const float*)d_in[3];
    float* out = (float*)d_out;

    cudaFuncSetAttribute(qkv_tc_kernel,
                         cudaFuncAttributeMaxDynamicSharedMemorySize, SMEM_DYN);
    cudaFuncSetAttribute(attn_proj_kernel,
                         cudaFuncAttributeMaxDynamicSharedMemorySize, FA_SMEM);

    const int ncvt = (N_X + N_QW + N_PW) / 4;
    cvt_all_kernel<<<(ncvt + 255) / 256, 256>>>(x, qkv_w, proj_w);

    // QKV projection -> Q(*scale*log2e)/K [B,H,N,D], Vt [B,H,D,N]
    qkv_tc_kernel<<<dim3(2304 / 128, MROWS / 128), 256, SMEM_DYN>>>();

    // Fused attention (768 blocks) + proj (384 blocks), dependency-tracked
    attn_proj_kernel<<<1152, 256, FA_SMEM>>>(proj_b, out);
}